// round 1
// baseline (speedup 1.0000x reference)
#include <cuda_runtime.h>
#include <math.h>
#include <stdint.h>

#define THREADS 512
#define M 8192            // packed complex FFT size
#define NFULL 16384       // real signal length
#define NBINS 8193        // rfft bins
#define ROWS 512
#define PI_D 3.14159265358979323846

// ---------------- global scratch / accumulators (no allocation allowed) ---------
__device__ double g_pear;
__device__ double g_cos;
__device__ double g_absdiff;
__device__ double g_tp;
__device__ double g_nmi;

__device__ float2 g_W2048[2048];    // e^{-2pi i k/8192}, k<2048 (rest by symmetry)
__device__ float2 g_WN[NBINS];      // e^{-i pi k/8192},  k=0..8192

// ---------------- complex helpers ----------------
__device__ __forceinline__ float2 cmul(float2 a, float2 b){
    return make_float2(a.x*b.x - a.y*b.y, a.x*b.y + a.y*b.x);
}
__device__ __forceinline__ float2 cconj(float2 a){ return make_float2(a.x, -a.y); }

__device__ __forceinline__ float warp_sum(float v){
    #pragma unroll
    for (int o = 16; o; o >>= 1) v += __shfl_down_sync(0xffffffffu, v, o);
    return v;
}

// ---------------- init kernels ----------------
__global__ void zero_acc_kernel(){
    g_pear = 0.0; g_cos = 0.0; g_absdiff = 0.0; g_tp = 0.0; g_nmi = 0.0;
}

__global__ void init_tw_kernel(){
    int k = blockIdx.x * blockDim.x + threadIdx.x;
    if (k < 2048){
        double a = -2.0 * PI_D * (double)k / 8192.0;
        g_W2048[k] = make_float2((float)cos(a), (float)sin(a));
    }
    if (k < NBINS){
        double a = -PI_D * (double)k / 8192.0;
        g_WN[k] = make_float2((float)cos(a), (float)sin(a));
    }
}

// ---------------- in-smem radix-2 FFT, size 8192, DIT, bit-reversed input ------
__device__ void fft8192(float2* Z, const float2* W, bool inverse){
    #pragma unroll 1
    for (int s = 1; s <= 13; s++){
        int half = 1 << (s - 1);
        int sh = 13 - s;
        #pragma unroll 1
        for (int j = threadIdx.x; j < 4096; j += THREADS){
            int t  = j & (half - 1);
            int i1 = ((j >> (s - 1)) << s) + t;
            int i2 = i1 + half;
            int k  = t << sh;                  // twiddle index in [0,4096)
            float2 w;
            if (k < 2048) w = W[k];
            else { float2 ww = W[k - 2048]; w = make_float2(ww.y, -ww.x); } // * e^{-i pi/2}
            if (inverse) w.y = -w.y;
            float2 u = Z[i1];
            float2 v = cmul(Z[i2], w);
            Z[i1] = make_float2(u.x + v.x, u.y + v.y);
            Z[i2] = make_float2(u.x - v.x, u.y - v.y);
        }
        __syncthreads();
    }
}

// Unpack: X[k] of the length-16384 real signal from packed Z (= FFT8192 of even+i*odd).
// w must be e^{-i pi k/8192}; valid for k in [0, 8192].
__device__ __forceinline__ float2 spec_at(const float2* Z, int k, float2 w){
    float2 a = Z[k & (M - 1)];
    float2 b = Z[(M - k) & (M - 1)];
    float2 E = make_float2(0.5f*(a.x + b.x),  0.5f*(a.y - b.y));
    float2 O = make_float2(0.5f*(a.y + b.y), -0.5f*(a.x - b.x));
    float2 WO = cmul(w, O);
    return make_float2(E.x + WO.x, E.y + WO.y);
}

// ---------------- main fused kernel: one CTA per row ----------------
__global__ __launch_bounds__(THREADS, 1)
void row_kernel(const float* __restrict__ pred, const float* __restrict__ targ,
                const int* __restrict__ pi){
    extern __shared__ float2 sm[];
    float2* Zp = sm;                    // 8192
    float2* Zt = sm + M;                // 8192
    float2* Cb = sm + 2*M;              // 8193
    float2* Wt = sm + 2*M + NBINS;      // 2048

    __shared__ float s_red[16][6];
    __shared__ int   s_idx[16];

    const int tid  = threadIdx.x;
    const int warp = tid >> 5, lane = tid & 31;
    const int row  = blockIdx.x;
    const int i0   = *pi;

    const float2* xr = (const float2*)(pred + ((size_t)i0 * ROWS + row) * (size_t)NFULL);
    const float2* yr = (const float2*)(targ + (size_t)row * (size_t)NFULL);

    // twiddle table -> smem
    #pragma unroll 1
    for (int k = tid; k < 2048; k += THREADS) Wt[k] = g_W2048[k];

    // ---- load (bit-reversed pack) + per-row Pearson moments ----
    float sx = 0.f, sy = 0.f, sxy = 0.f, sx2 = 0.f, sy2 = 0.f;
    #pragma unroll 1
    for (int n = tid; n < M; n += THREADS){
        float2 a = xr[n], b = yr[n];
        sx  += a.x + a.y;          sy  += b.x + b.y;
        sxy += a.x*b.x + a.y*b.y;
        sx2 += a.x*a.x + a.y*a.y;  sy2 += b.x*b.x + b.y*b.y;
        int r = __brev(n) >> 19;   // 13-bit reversal
        Zp[r] = a; Zt[r] = b;
    }
    sx  = warp_sum(sx);  sy  = warp_sum(sy); sxy = warp_sum(sxy);
    sx2 = warp_sum(sx2); sy2 = warp_sum(sy2);
    if (lane == 0){
        s_red[warp][0]=sx; s_red[warp][1]=sy; s_red[warp][2]=sxy;
        s_red[warp][3]=sx2; s_red[warp][4]=sy2;
    }
    __syncthreads();
    if (tid == 0){
        double Sx=0,Sy=0,Sxy=0,Sx2=0,Sy2=0;
        for (int w = 0; w < 16; w++){
            Sx+=s_red[w][0]; Sy+=s_red[w][1]; Sxy+=s_red[w][2];
            Sx2+=s_red[w][3]; Sy2+=s_red[w][4];
        }
        const double N = (double)NFULL;
        double pear = (N*Sxy - Sx*Sy) / sqrt((N*Sx2 - Sx*Sx) * (N*Sy2 - Sy*Sy));
        atomicAdd(&g_pear, 1.0 - pear);
    }
    __syncthreads();

    // ---- forward FFTs (unnormalized DFT == jnp.fft.rfft convention) ----
    fft8192(Zp, Wt, false);
    fft8192(Zt, Wt, false);

    // ---- spectra: power-spectrum sums + hann-windowed phase correlation ----
    float accd = 0.f, acct = 0.f;
    #pragma unroll 1
    for (int k = tid; k <= 8192; k += THREADS){
        float2 w0 = g_WN[k];
        float2 X0p = spec_at(Zp, k, w0);
        float2 X0t = spec_at(Zt, k, w0);
        float2 Xmp, Xmt, Xpp, Xpt;
        if (k == 0){
            float2 w1 = g_WN[1];
            Xmp = cconj(spec_at(Zp, 1, w1));    // X[-1] = conj(X[1])
            Xmt = cconj(spec_at(Zt, 1, w1));
        } else {
            float2 wm = g_WN[k-1];
            Xmp = spec_at(Zp, k-1, wm);
            Xmt = spec_at(Zt, k-1, wm);
        }
        if (k == 8192){
            float2 w1 = g_WN[8191];
            Xpp = cconj(spec_at(Zp, 8191, w1)); // X[8193] = conj(X[8191])
            Xpt = cconj(spec_at(Zt, 8191, w1));
        } else {
            float2 wp = g_WN[k+1];
            Xpp = spec_at(Zp, k+1, wp);
            Xpt = spec_at(Zt, k+1, wp);
        }
        // power spectrum (un-windowed)
        float pp = X0p.x*X0p.x + X0p.y*X0p.y;
        float pt = X0t.x*X0t.x + X0t.y*X0t.y;
        accd += fabsf(pp - pt);
        acct += pt;
        // hann window in frequency: 0.5*X[k] - 0.25*(X[k-1]+X[k+1])
        float2 xf = make_float2(0.5f*X0p.x - 0.25f*(Xmp.x + Xpp.x),
                                0.5f*X0p.y - 0.25f*(Xmp.y + Xpp.y));
        float2 tf = make_float2(0.5f*X0t.x - 0.25f*(Xmt.x + Xpt.x),
                                0.5f*X0t.y - 0.25f*(Xmt.y + Xpt.y));
        float2 c = cmul(xf, cconj(tf));
        float inv = rsqrtf(c.x*c.x + c.y*c.y);
        Cb[k] = make_float2(c.x*inv, c.y*inv);   // phase-only correlation
    }
    accd = warp_sum(accd); acct = warp_sum(acct);
    if (lane == 0){ s_red[warp][0] = accd; s_red[warp][1] = acct; }
    __syncthreads();
    if (tid == 0){
        double d = 0.0, t2 = 0.0;
        for (int w = 0; w < 16; w++){ d += s_red[w][0]; t2 += s_red[w][1]; }
        atomicAdd(&g_absdiff, d);
        atomicAdd(&g_tp, t2);
    }
    __syncthreads();

    // ---- pack spectrum back for real inverse FFT (into Zp, bit-reversed) ----
    #pragma unroll 1
    for (int k = tid; k < M; k += THREADS){
        float2 Ck  = Cb[k];
        float2 Ck2 = (k == 0) ? Cb[8192] : cconj(Cb[8192 - k]);  // C[k+8192]
        float2 E = make_float2(0.5f*(Ck.x + Ck2.x), 0.5f*(Ck.y + Ck2.y));
        float2 D = make_float2(0.5f*(Ck.x - Ck2.x), 0.5f*(Ck.y - Ck2.y));
        float2 wn = cconj(g_WN[k]);             // e^{+i pi k/8192}
        float2 O  = cmul(wn, D);
        Zp[__brev(k) >> 19] = make_float2(E.x - O.y, E.y + O.x);  // E + i*O
    }
    __syncthreads();
    fft8192(Zp, Wt, true);   // unnormalized IDFT; positive scale -> argmax invariant

    // ---- argmax over 16384 real samples (first-occurrence tie break) ----
    float best = -INFINITY; int bi = 0x7fffffff;
    #pragma unroll 1
    for (int n = tid; n < M; n += THREADS){
        float2 z = Zp[n];                 // y[2n] = Re, y[2n+1] = Im
        int e = 2*n, o = 2*n + 1;
        if (z.x > best || (z.x == best && e < bi)){ best = z.x; bi = e; }
        if (z.y > best || (z.y == best && o < bi)){ best = z.y; bi = o; }
    }
    #pragma unroll
    for (int off = 16; off; off >>= 1){
        float ov = __shfl_down_sync(0xffffffffu, best, off);
        int   oi = __shfl_down_sync(0xffffffffu, bi,   off);
        if (ov > best || (ov == best && oi < bi)){ best = ov; bi = oi; }
    }
    if (lane == 0){ s_red[warp][0] = best; s_idx[warp] = bi; }
    __syncthreads();
    if (tid == 0){
        best = s_red[0][0]; bi = s_idx[0];
        for (int w = 1; w < 16; w++){
            float v = s_red[w][0]; int ix = s_idx[w];
            if (v > best || (v == best && ix < bi)){ best = v; bi = ix; }
        }
        atomicAdd(&g_cos, (double)cosf(2.0f * (float)PI_D * (float)bi / 16384.0f));
    }
}

// ---------------- mutual information kernel: one CTA per row ----------------
__global__ __launch_bounds__(THREADS)
void mi_kernel(const float* __restrict__ pred, const float* __restrict__ targ,
               const int* __restrict__ pi){
    __shared__ float s_red[16][4];
    __shared__ float s_mm[4];            // xmin,xmax,ymin,ymax
    __shared__ unsigned hist[100];

    const int tid = threadIdx.x;
    const int warp = tid >> 5, lane = tid & 31;
    const int row = blockIdx.x;
    const int i0 = *pi;
    const float* x = pred + ((size_t)i0 * ROWS + row) * (size_t)NFULL;
    const float* y = targ + (size_t)row * (size_t)NFULL;

    if (tid < 100) hist[tid] = 0u;

    float xmn = INFINITY, xmx = -INFINITY, ymn = INFINITY, ymx = -INFINITY;
    #pragma unroll 1
    for (int n = tid; n < NFULL; n += THREADS){
        float a = x[n], b = y[n];
        xmn = fminf(xmn, a); xmx = fmaxf(xmx, a);
        ymn = fminf(ymn, b); ymx = fmaxf(ymx, b);
    }
    #pragma unroll
    for (int o = 16; o; o >>= 1){
        xmn = fminf(xmn, __shfl_down_sync(0xffffffffu, xmn, o));
        xmx = fmaxf(xmx, __shfl_down_sync(0xffffffffu, xmx, o));
        ymn = fminf(ymn, __shfl_down_sync(0xffffffffu, ymn, o));
        ymx = fmaxf(ymx, __shfl_down_sync(0xffffffffu, ymx, o));
    }
    if (lane == 0){ s_red[warp][0]=xmn; s_red[warp][1]=xmx; s_red[warp][2]=ymn; s_red[warp][3]=ymx; }
    __syncthreads();
    if (tid == 0){
        float a = s_red[0][0], b = s_red[0][1], c = s_red[0][2], d = s_red[0][3];
        for (int w = 1; w < 16; w++){
            a = fminf(a, s_red[w][0]); b = fmaxf(b, s_red[w][1]);
            c = fminf(c, s_red[w][2]); d = fmaxf(d, s_red[w][3]);
        }
        s_mm[0]=a; s_mm[1]=b; s_mm[2]=c; s_mm[3]=d;
    }
    __syncthreads();

    const float xmin = s_mm[0], ymin = s_mm[2];
    const float bwx = __fdiv_rn(s_mm[1] - s_mm[0], 10.0f);
    const float bwy = __fdiv_rn(s_mm[3] - s_mm[2], 10.0f);

    #pragma unroll 1
    for (int n = tid; n < NFULL; n += THREADS){
        int ix = (int)__fdiv_rn(x[n] - xmin, bwx);
        int iy = (int)__fdiv_rn(y[n] - ymin, bwy);
        ix = min(max(ix, 0), 9);
        iy = min(max(iy, 0), 9);
        atomicAdd(&hist[ix * 10 + iy], 1u);
    }
    __syncthreads();

    if (tid == 0){
        const float eps = 1e-8f;
        const float denom = 8388608.0f;  // B*S = 512*16384 (faithful to reference)
        float hx[10], hy[10];
        for (int a = 0; a < 10; a++){ hx[a] = 0.f; hy[a] = 0.f; }
        for (int a = 0; a < 10; a++)
            for (int b = 0; b < 10; b++){
                float h = (float)hist[a*10 + b];
                hx[a] += h; hy[b] += h;
            }
        float mi = 0.f;
        for (int a = 0; a < 10; a++){
            float px = hx[a] / denom;
            for (int b = 0; b < 10; b++){
                float py  = hy[b] / denom;
                float pxy = (float)hist[a*10 + b] / denom;
                mi += pxy * logf(__fdiv_rn(pxy + eps, px * py + eps));
            }
        }
        float hxe = 0.f, hye = 0.f;
        for (int a = 0; a < 10; a++){
            float px = hx[a] / denom, py = hy[a] / denom;
            hxe -= px * logf(px + eps);
            hye -= py * logf(py + eps);
        }
        float nmi = mi / (0.5f * (hxe + hye));
        atomicAdd(&g_nmi, (double)nmi);
    }
}

// ---------------- finalize ----------------
__global__ void finalize_kernel(const int* __restrict__ pep, float* __restrict__ out){
    double loss = g_pear / (double)ROWS;
    int ep = *pep;
    if (ep >= 400){
        loss += 1.0 - g_cos / (double)ROWS;     // phase correlation
        loss += g_absdiff / g_tp;               // power spectrum
    }
    if (ep >= 700){
        loss += 1.0 - g_nmi / (double)ROWS;     // mutual information
    }
    out[0] = (float)loss;
}

// ---------------- launch ----------------
extern "C" void kernel_launch(void* const* d_in, const int* in_sizes, int n_in,
                              void* d_out, int out_size){
    const float* pred = (const float*)d_in[0];
    const float* targ = (const float*)d_in[1];
    const int*   pi   = (const int*)d_in[2];
    const int*   pep  = (const int*)d_in[3];
    float* out = (float*)d_out;

    const size_t smem_bytes = (size_t)(2*M + NBINS + 2048) * sizeof(float2); // 213000
    cudaFuncSetAttribute(row_kernel, cudaFuncAttributeMaxDynamicSharedMemorySize,
                         (int)smem_bytes);

    zero_acc_kernel<<<1, 1>>>();
    init_tw_kernel<<<(NBINS + 255) / 256, 256>>>();
    row_kernel<<<ROWS, THREADS, smem_bytes>>>(pred, targ, pi);
    mi_kernel<<<ROWS, THREADS>>>(pred, targ, pi);
    finalize_kernel<<<1, 1>>>(pep, out);
}